// round 13
// baseline (speedup 1.0000x reference)
#include <cuda_runtime.h>
#include <cuda_bf16.h>
#include <cstdint>

#define D4 32               // float4 per full row (D=128)
#define QPC 8               // float4-quads per CTA (32 cols = 128B contiguous/row)
#define THREADS 512
#define RB2 (THREADS / QPC) // 64 row-bases for pass 2
#define RB1 (THREADS / 4)   // 128 row-bases for pass 1 (32B/thread)
#define NWARP (THREADS / 32)

// pass-1 load: plain 256-bit load (normal LRU; width = fewer LDGs, higher MLP)
__device__ __forceinline__ void ld_v8(const float* p, float4& a, float4& b) {
    uint32_t r0, r1, r2, r3, r4, r5, r6, r7;
    asm("ld.global.v8.b32 {%0,%1,%2,%3,%4,%5,%6,%7}, [%8];"
        : "=r"(r0), "=r"(r1), "=r"(r2), "=r"(r3),
          "=r"(r4), "=r"(r5), "=r"(r6), "=r"(r7) : "l"(p));
    a.x = __uint_as_float(r0); a.y = __uint_as_float(r1);
    a.z = __uint_as_float(r2); a.w = __uint_as_float(r3);
    b.x = __uint_as_float(r4); b.y = __uint_as_float(r5);
    b.z = __uint_as_float(r6); b.w = __uint_as_float(r7);
}

__global__ __launch_bounds__(THREADS, 4)
void graphnorm_v8(const float* __restrict__ x,
                  const float* __restrict__ gamma,
                  const float* __restrict__ beta,
                  const int* __restrict__ batch,
                  float* __restrict__ out)
{
    __shared__ float4 psum[NWARP][QPC];
    __shared__ float4 psq [NWARP][QPC];
    __shared__ float4 smean[QPC], sinv[QPC];

    const int cb   = blockIdx.x;                  // column block 0..3 (fastest)
    const int g    = blockIdx.y;                  // graph
    const int warp = threadIdx.x >> 5;
    const int lane = threadIdx.x & 31;

    const int start = batch[g];
    const int end   = batch[g + 1];
    const int cnt   = end - start;
    const float fcnt = (float)cnt;

    const float* __restrict__ xs = x;
    const float4* __restrict__ xv = (const float4*)x;
    float4* __restrict__ ov = (float4*)out;

    // ---- pass 1: 32B/thread plain v8 reads, accumulate sum / sumsq ----
    const int oct = threadIdx.x & 3;              // 32B chunk within 128B row
    const int rb1 = threadIdx.x >> 2;             // 0..127
    const long coloct = (long)cb * 32 + oct * 8;  // float col of this 32B chunk

    float4 sa = make_float4(0.f, 0.f, 0.f, 0.f);
    float4 sb = make_float4(0.f, 0.f, 0.f, 0.f);
    float4 qa = make_float4(0.f, 0.f, 0.f, 0.f);
    float4 qb = make_float4(0.f, 0.f, 0.f, 0.f);
    for (int r = rb1; r < cnt; r += RB1) {
        float4 va, vb;
        ld_v8(&xs[(long)(start + r) * 128 + coloct], va, vb);
        sa.x += va.x; sa.y += va.y; sa.z += va.z; sa.w += va.w;
        qa.x += va.x * va.x; qa.y += va.y * va.y; qa.z += va.z * va.z; qa.w += va.w * va.w;
        sb.x += vb.x; sb.y += vb.y; sb.z += vb.z; sb.w += vb.w;
        qb.x += vb.x * vb.x; qb.y += vb.y * vb.y; qb.z += vb.z * vb.z; qb.w += vb.w * vb.w;
    }

    // ---- warp reduce: lanes {oct, oct+4, ..., oct+28} share a 32B chunk ----
    #pragma unroll
    for (int off = 4; off <= 16; off <<= 1) {
        sa.x += __shfl_xor_sync(0xffffffffu, sa.x, off);
        sa.y += __shfl_xor_sync(0xffffffffu, sa.y, off);
        sa.z += __shfl_xor_sync(0xffffffffu, sa.z, off);
        sa.w += __shfl_xor_sync(0xffffffffu, sa.w, off);
        sb.x += __shfl_xor_sync(0xffffffffu, sb.x, off);
        sb.y += __shfl_xor_sync(0xffffffffu, sb.y, off);
        sb.z += __shfl_xor_sync(0xffffffffu, sb.z, off);
        sb.w += __shfl_xor_sync(0xffffffffu, sb.w, off);
        qa.x += __shfl_xor_sync(0xffffffffu, qa.x, off);
        qa.y += __shfl_xor_sync(0xffffffffu, qa.y, off);
        qa.z += __shfl_xor_sync(0xffffffffu, qa.z, off);
        qa.w += __shfl_xor_sync(0xffffffffu, qa.w, off);
        qb.x += __shfl_xor_sync(0xffffffffu, qb.x, off);
        qb.y += __shfl_xor_sync(0xffffffffu, qb.y, off);
        qb.z += __shfl_xor_sync(0xffffffffu, qb.z, off);
        qb.w += __shfl_xor_sync(0xffffffffu, qb.w, off);
    }
    // lane oct (0..3) holds chunk totals: two float4 quads (2*oct, 2*oct+1)
    if (lane < 4) {
        psum[warp][2 * lane]     = sa;
        psum[warp][2 * lane + 1] = sb;
        psq [warp][2 * lane]     = qa;
        psq [warp][2 * lane + 1] = qb;
    }
    __syncthreads();

    // ---- final reduce across warps + stats (QPC threads, one per quad) ----
    if (threadIdx.x < QPC) {
        float4 ts = make_float4(0.f, 0.f, 0.f, 0.f);
        float4 tq = make_float4(0.f, 0.f, 0.f, 0.f);
        #pragma unroll
        for (int w = 0; w < NWARP; w++) {
            float4 a = psum[w][threadIdx.x];
            float4 b = psq [w][threadIdx.x];
            ts.x += a.x; ts.y += a.y; ts.z += a.z; ts.w += a.w;
            tq.x += b.x; tq.y += b.y; tq.z += b.z; tq.w += b.w;
        }
        float4 m, iv;
        m.x = ts.x / fcnt; m.y = ts.y / fcnt; m.z = ts.z / fcnt; m.w = ts.w / fcnt;
        float denom = fcnt - 1.0f;
        iv.x = 1.0f / (sqrtf(fmaxf((tq.x - fcnt * m.x * m.x) / denom, 0.f)) + 1e-5f);
        iv.y = 1.0f / (sqrtf(fmaxf((tq.y - fcnt * m.y * m.y) / denom, 0.f)) + 1e-5f);
        iv.z = 1.0f / (sqrtf(fmaxf((tq.z - fcnt * m.z * m.z) / denom, 0.f)) + 1e-5f);
        iv.w = 1.0f / (sqrtf(fmaxf((tq.w - fcnt * m.w * m.w) / denom, 0.f)) + 1e-5f);
        smean[threadIdx.x] = m;
        sinv [threadIdx.x] = iv;
    }
    __syncthreads();

    // ---- pass 2: re-read (L2, evict-first), streaming store (as in R6) ----
    const int quad = threadIdx.x & (QPC - 1);     // 0..7
    const int rb2  = threadIdx.x >> 3;            // 0..63
    const long colq = (long)cb * QPC + quad;      // float4 col 0..31

    const float4 g4 = ((const float4*)gamma)[colq];
    const float4 b4 = ((const float4*)beta)[colq];
    const float4 m  = smean[quad];
    const float4 iv = sinv [quad];

    for (int r = rb2; r < cnt; r += RB2) {
        const long idx = (long)(start + r) * D4 + colq;
        float4 v = __ldcs(&xv[idx]);          // evict-first: dead after this read
        float4 o;
        o.x = g4.x * (v.x - m.x) * iv.x + b4.x;
        o.y = g4.y * (v.y - m.y) * iv.y + b4.y;
        o.z = g4.z * (v.z - m.z) * iv.z + b4.z;
        o.w = g4.w * (v.w - m.w) * iv.w + b4.w;
        __stcs(&ov[idx], o);                  // streaming store, no L2 pollution
    }
}

extern "C" void kernel_launch(void* const* d_in, const int* in_sizes, int n_in,
                              void* d_out, int out_size)
{
    const float* x     = (const float*)d_in[0];
    const float* gamma = (const float*)d_in[1];
    const float* beta  = (const float*)d_in[2];
    const int*   batch = (const int*)d_in[3];
    float* out = (float*)d_out;

    const int G = in_sizes[3] - 1;
    dim3 grid(D4 / QPC, G);   // (column-block fastest, graph)
    graphnorm_v8<<<grid, THREADS>>>(x, gamma, beta, batch, out);
}